// round 11
// baseline (speedup 1.0000x reference)
#include <cuda_runtime.h>
#include <cuda_fp16.h>
#include <cstdint>

#define N_NODES  100000
#define N_HEDGES 25000
#define NNZ      1600000
#define CH       128

#define NB_E ((N_HEDGES + 1023) / 1024)   // 25
#define NB_V ((N_NODES  + 1023) / 1024)   // 98

// ---------------------------------------------------------------------------
// Device-global scratch
// ---------------------------------------------------------------------------
__device__ __half g_Xh[(size_t)N_NODES * CH];   // fp16 X            (25.6 MB)
__device__ __half g_Wh[CH * CH];                // fp16 Wlin
__device__ __half g_Yh[(size_t)N_HEDGES * CH];  // fp16 seg1 output  ( 6.4 MB)
__device__ __half g_Zh[(size_t)N_HEDGES * CH];  // fp16 GEMM output  ( 6.4 MB)

__device__ int g_cnt_e[N_HEDGES];
__device__ int g_cnt_v[N_NODES];
__device__ int g_rowptr_e[N_HEDGES + 1];
__device__ int g_rowptr_v[N_NODES + 1];
__device__ unsigned short g_rank_e[NNZ];
__device__ unsigned short g_rank_v[NNZ];
__device__ int            g_src_by_e[NNZ];   // node ids (need 17 bits)
__device__ unsigned short g_dst_by_v[NNZ];   // hyperedge ids (< 25000, fits u16)
__device__ int g_part_e[128];
__device__ int g_boff_e[128];
__device__ int g_part_v[128];
__device__ int g_boff_v[128];
__device__ int g_sync_e[2];
__device__ int g_sync_v[2];

// ---------------------------------------------------------------------------
// fp32 -> fp16 convert: X and Wlin in one launch
// ---------------------------------------------------------------------------
__global__ __launch_bounds__(256) void convertAll_kernel(const float* __restrict__ X,
                                                         const float* __restrict__ W) {
    const size_t nX8 = (size_t)N_NODES * CH / 8;
    const size_t nW8 = (size_t)CH * CH / 8;
    size_t t = (size_t)blockIdx.x * blockDim.x + threadIdx.x;
    const float* srcp;
    __half* dstp;
    size_t i;
    if (t < nX8) { srcp = X; dstp = g_Xh; i = t * 8; }
    else if (t < nX8 + nW8) { srcp = W; dstp = g_Wh; i = (t - nX8) * 8; }
    else return;
    float4 a = *reinterpret_cast<const float4*>(srcp + i);
    float4 b = *reinterpret_cast<const float4*>(srcp + i + 4);
    __half2 h[4];
    h[0] = __floats2half2_rn(a.x, a.y);
    h[1] = __floats2half2_rn(a.z, a.w);
    h[2] = __floats2half2_rn(b.x, b.y);
    h[3] = __floats2half2_rn(b.z, b.w);
    *reinterpret_cast<uint4*>(dstp + i) = *reinterpret_cast<uint4*>(h);
}

// ---------------------------------------------------------------------------
// Combined histogram + rank tickets, 8 edges/thread (16 atomics in flight).
// ---------------------------------------------------------------------------
__global__ void hist_kernel(const int4* __restrict__ src4, const int4* __restrict__ dst4) {
    int i = blockIdx.x * blockDim.x + threadIdx.x;
    if (i >= NNZ / 8) return;
    int4 s0 = __ldg(&src4[i * 2 + 0]);
    int4 s1 = __ldg(&src4[i * 2 + 1]);
    int4 d0 = __ldg(&dst4[i * 2 + 0]);
    int4 d1 = __ldg(&dst4[i * 2 + 1]);

    unsigned short re[8], rv[8];
    re[0] = (unsigned short)atomicAdd(&g_cnt_e[d0.x], 1);
    re[1] = (unsigned short)atomicAdd(&g_cnt_e[d0.y], 1);
    re[2] = (unsigned short)atomicAdd(&g_cnt_e[d0.z], 1);
    re[3] = (unsigned short)atomicAdd(&g_cnt_e[d0.w], 1);
    re[4] = (unsigned short)atomicAdd(&g_cnt_e[d1.x], 1);
    re[5] = (unsigned short)atomicAdd(&g_cnt_e[d1.y], 1);
    re[6] = (unsigned short)atomicAdd(&g_cnt_e[d1.z], 1);
    re[7] = (unsigned short)atomicAdd(&g_cnt_e[d1.w], 1);
    rv[0] = (unsigned short)atomicAdd(&g_cnt_v[s0.x], 1);
    rv[1] = (unsigned short)atomicAdd(&g_cnt_v[s0.y], 1);
    rv[2] = (unsigned short)atomicAdd(&g_cnt_v[s0.z], 1);
    rv[3] = (unsigned short)atomicAdd(&g_cnt_v[s0.w], 1);
    rv[4] = (unsigned short)atomicAdd(&g_cnt_v[s1.x], 1);
    rv[5] = (unsigned short)atomicAdd(&g_cnt_v[s1.y], 1);
    rv[6] = (unsigned short)atomicAdd(&g_cnt_v[s1.z], 1);
    rv[7] = (unsigned short)atomicAdd(&g_cnt_v[s1.w], 1);

    *reinterpret_cast<uint4*>(g_rank_e + i * 8) = *reinterpret_cast<uint4*>(re);
    *reinterpret_cast<uint4*>(g_rank_v + i * 8) = *reinterpret_cast<uint4*>(rv);
}

// ---------------------------------------------------------------------------
// One-pass scan (per side). nblk blocks, all resident.
// ---------------------------------------------------------------------------
__global__ __launch_bounds__(1024) void scan_kernel(const int* __restrict__ cnt, int n,
                                                    int* __restrict__ rowptr,
                                                    int* __restrict__ part,
                                                    int* __restrict__ boff,
                                                    int* __restrict__ sync, int nblk) {
    __shared__ int warpsum[32];
    __shared__ int p[128];
    __shared__ int sh_flag;
    __shared__ int sh_boff;

    const int tid  = threadIdx.x;
    const int bid  = blockIdx.x;
    const int i    = bid * 1024 + tid;
    const int v0   = (i < n) ? cnt[i] : 0;
    const int lane = tid & 31;
    const int warp = tid >> 5;

    int x = v0;
#pragma unroll
    for (int o = 1; o < 32; o <<= 1) {
        int y = __shfl_up_sync(0xffffffffu, x, o);
        if (lane >= o) x += y;
    }
    if (lane == 31) warpsum[warp] = x;
    __syncthreads();
    if (warp == 0) {
        int w = warpsum[lane];
#pragma unroll
        for (int o = 1; o < 32; o <<= 1) {
            int y = __shfl_up_sync(0xffffffffu, w, o);
            if (lane >= o) w += y;
        }
        warpsum[lane] = w;
    }
    __syncthreads();
    const int incl = x + (warp ? warpsum[warp - 1] : 0);

    if (tid == 1023) {
        part[bid] = incl;
        __threadfence();
        int ticket = atomicAdd(&sync[0], 1);
        sh_flag = (ticket == nblk - 1);
    }
    __syncthreads();

    if (sh_flag) {
        int mine = 0;
        if (tid < nblk) {
            mine = atomicAdd(&part[tid], 0);
            p[tid] = mine;
        }
        __syncthreads();
#pragma unroll
        for (int o = 1; o < 128; o <<= 1) {
            int add = (tid < nblk && tid >= o) ? p[tid - o] : 0;
            __syncthreads();
            if (tid < nblk) p[tid] += add;
            __syncthreads();
        }
        if (tid < nblk) boff[tid] = p[tid] - mine;
        if (tid == nblk - 1) rowptr[n] = p[tid];
        __threadfence();
        if (tid == 0) atomicExch(&sync[1], 1);
    }

    if (tid == 0) {
        while (atomicAdd(&sync[1], 0) == 0) __nanosleep(64);
        sh_boff = atomicAdd(&boff[bid], 0);
    }
    __syncthreads();

    if (i < n) rowptr[i] = incl - v0 + sh_boff;
}

// ---------------------------------------------------------------------------
// ATOMIC-FREE placement: pos = rowptr[seg] + rank  (4 edges / thread)
// ---------------------------------------------------------------------------
__global__ void placeE_kernel(const int4* __restrict__ src4, const int4* __restrict__ dst4) {
    int i = blockIdx.x * blockDim.x + threadIdx.x;
    if (i >= NNZ / 4) return;
    int4 s = __ldg(&src4[i]);
    int4 d = __ldg(&dst4[i]);
    ushort4 r = *reinterpret_cast<const ushort4*>(g_rank_e + i * 4);
    g_src_by_e[__ldg(&g_rowptr_e[d.x]) + r.x] = s.x;
    g_src_by_e[__ldg(&g_rowptr_e[d.y]) + r.y] = s.y;
    g_src_by_e[__ldg(&g_rowptr_e[d.z]) + r.z] = s.z;
    g_src_by_e[__ldg(&g_rowptr_e[d.w]) + r.w] = s.w;
}

__global__ void placeV_kernel(const int4* __restrict__ src4, const int4* __restrict__ dst4) {
    int i = blockIdx.x * blockDim.x + threadIdx.x;
    if (i >= NNZ / 4) return;
    int4 s = __ldg(&src4[i]);
    int4 d = __ldg(&dst4[i]);
    ushort4 r = *reinterpret_cast<const ushort4*>(g_rank_v + i * 4);
    g_dst_by_v[__ldg(&g_rowptr_v[s.x]) + r.x] = (unsigned short)d.x;
    g_dst_by_v[__ldg(&g_rowptr_v[s.y]) + r.y] = (unsigned short)d.y;
    g_dst_by_v[__ldg(&g_rowptr_v[s.z]) + r.z] = (unsigned short)d.z;
    g_dst_by_v[__ldg(&g_rowptr_v[s.w]) + r.w] = (unsigned short)d.w;
}

// ---------------------------------------------------------------------------
// Stage 1: warp per hyperedge (16 lanes x uint4, warp-halves alternate edges)
// ---------------------------------------------------------------------------
__global__ __launch_bounds__(256) void seg1_kernel(const float* __restrict__ degE,
                                                   const float* __restrict__ Wbuf) {
    int gid  = blockIdx.x * blockDim.x + threadIdx.x;
    int e    = gid >> 5;
    int lane = gid & 31;
    if (e >= N_HEDGES) return;
    int half = lane >> 4;
    int sub  = lane & 15;

    int beg = g_rowptr_e[e];
    int end = g_rowptr_e[e + 1];
    const uint4* Xh4 = reinterpret_cast<const uint4*>(g_Xh);

    float acc[8];
#pragma unroll
    for (int j = 0; j < 8; j++) acc[j] = 0.f;

    int i = beg + half;
    for (; i + 6 < end; i += 8) {
        int s0 = __ldg(&g_src_by_e[i + 0]);
        int s1 = __ldg(&g_src_by_e[i + 2]);
        int s2 = __ldg(&g_src_by_e[i + 4]);
        int s3 = __ldg(&g_src_by_e[i + 6]);
        uint4 u0 = __ldg(&Xh4[(size_t)s0 * 16 + sub]);
        uint4 u1 = __ldg(&Xh4[(size_t)s1 * 16 + sub]);
        uint4 u2 = __ldg(&Xh4[(size_t)s2 * 16 + sub]);
        uint4 u3 = __ldg(&Xh4[(size_t)s3 * 16 + sub]);
#pragma unroll
        for (int j = 0; j < 4; j++) {
            uint4 u = (j == 0) ? u0 : (j == 1) ? u1 : (j == 2) ? u2 : u3;
            const __half2* h = reinterpret_cast<const __half2*>(&u);
#pragma unroll
            for (int q = 0; q < 4; q++) {
                float2 f = __half22float2(h[q]);
                acc[q * 2]     += f.x;
                acc[q * 2 + 1] += f.y;
            }
        }
    }
    for (; i < end; i += 2) {
        int s = __ldg(&g_src_by_e[i]);
        uint4 u = __ldg(&Xh4[(size_t)s * 16 + sub]);
        const __half2* h = reinterpret_cast<const __half2*>(&u);
#pragma unroll
        for (int q = 0; q < 4; q++) {
            float2 f = __half22float2(h[q]);
            acc[q * 2]     += f.x;
            acc[q * 2 + 1] += f.y;
        }
    }

#pragma unroll
    for (int j = 0; j < 8; j++)
        acc[j] += __shfl_xor_sync(0xffffffffu, acc[j], 16);

    if (half == 0) {
        float sc = degE[e] * Wbuf[e];
        __half2 h[4];
#pragma unroll
        for (int q = 0; q < 4; q++)
            h[q] = __floats2half2_rn(acc[q * 2] * sc, acc[q * 2 + 1] * sc);
        *reinterpret_cast<uint4*>(g_Yh + (size_t)e * CH + sub * 8) =
            *reinterpret_cast<uint4*>(h);
    }
}

// ---------------------------------------------------------------------------
// HMMA GEMM: Zh = Yh @ Wh (fp16 in, fp32 accum, fp16 out)
// ---------------------------------------------------------------------------
#define GS 136

__global__ __launch_bounds__(256) void gemm_hmma_kernel() {
    extern __shared__ __half dsm[];
    __half* As = dsm;
    __half* Bs = dsm + 128 * GS;

    const int tid  = threadIdx.x;
    const int warp = tid >> 5;
    const int lane = tid & 31;
    const int row0 = blockIdx.x * 128;

    for (int t = tid; t < 128 * 16; t += 256) {
        int r = t >> 4;
        int c = (t & 15) * 8;
        uint4 v = make_uint4(0, 0, 0, 0);
        if (row0 + r < N_HEDGES)
            v = *reinterpret_cast<const uint4*>(g_Yh + (size_t)(row0 + r) * CH + c);
        *reinterpret_cast<uint4*>(&As[r * GS + c]) = v;
        *reinterpret_cast<uint4*>(&Bs[r * GS + c]) =
            *reinterpret_cast<const uint4*>(g_Wh + (size_t)r * CH + c);
    }
    __syncthreads();

    const int m0 = warp * 16;
    float acc[16][4];
#pragma unroll
    for (int t = 0; t < 16; t++)
#pragma unroll
        for (int j = 0; j < 4; j++) acc[t][j] = 0.f;

#pragma unroll
    for (int k0 = 0; k0 < 128; k0 += 16) {
        uint32_t a[4];
        {
            uint32_t addr = (uint32_t)__cvta_generic_to_shared(
                &As[(m0 + (lane & 15)) * GS + k0 + (lane >> 4) * 8]);
            asm volatile("ldmatrix.sync.aligned.m8n8.x4.shared.b16 {%0,%1,%2,%3}, [%4];"
                         : "=r"(a[0]), "=r"(a[1]), "=r"(a[2]), "=r"(a[3]) : "r"(addr));
        }
#pragma unroll
        for (int n0 = 0; n0 < 128; n0 += 16) {
            uint32_t b[4];
            uint32_t addr = (uint32_t)__cvta_generic_to_shared(
                &Bs[(k0 + (lane & 15)) * GS + n0 + (lane >> 4) * 8]);
            asm volatile("ldmatrix.sync.aligned.m8n8.x4.trans.shared.b16 {%0,%1,%2,%3}, [%4];"
                         : "=r"(b[0]), "=r"(b[1]), "=r"(b[2]), "=r"(b[3]) : "r"(addr));
            int t0 = n0 >> 3;
            asm volatile("mma.sync.aligned.m16n8k16.row.col.f32.f16.f16.f32 "
                         "{%0,%1,%2,%3},{%4,%5,%6,%7},{%8,%9},{%0,%1,%2,%3};"
                         : "+f"(acc[t0][0]), "+f"(acc[t0][1]), "+f"(acc[t0][2]), "+f"(acc[t0][3])
                         : "r"(a[0]), "r"(a[1]), "r"(a[2]), "r"(a[3]), "r"(b[0]), "r"(b[1]));
            asm volatile("mma.sync.aligned.m16n8k16.row.col.f32.f16.f16.f32 "
                         "{%0,%1,%2,%3},{%4,%5,%6,%7},{%8,%9},{%0,%1,%2,%3};"
                         : "+f"(acc[t0+1][0]), "+f"(acc[t0+1][1]), "+f"(acc[t0+1][2]), "+f"(acc[t0+1][3])
                         : "r"(a[0]), "r"(a[1]), "r"(a[2]), "r"(a[3]), "r"(b[2]), "r"(b[3]));
        }
    }

    const int groupID = lane >> 2;
    const int tig     = lane & 3;
    const int rowA = row0 + m0 + groupID;
    const int rowB = rowA + 8;
#pragma unroll
    for (int t = 0; t < 16; t++) {
        int col = t * 8 + tig * 2;
        if (rowA < N_HEDGES)
            *reinterpret_cast<__half2*>(g_Zh + (size_t)rowA * CH + col) =
                __floats2half2_rn(acc[t][0], acc[t][1]);
        if (rowB < N_HEDGES)
            *reinterpret_cast<__half2*>(g_Zh + (size_t)rowB * CH + col) =
                __floats2half2_rn(acc[t][2], acc[t][3]);
    }
}

// ---------------------------------------------------------------------------
// Stage 2: warp per node, 4-deep gather unroll, u16 index stream.
// ---------------------------------------------------------------------------
__global__ __launch_bounds__(256) void seg2_kernel(const float* __restrict__ degV,
                                                   float* __restrict__ out) {
    int gid  = blockIdx.x * blockDim.x + threadIdx.x;
    int v    = gid >> 5;
    int lane = gid & 31;
    if (v >= N_NODES) return;
    int half = lane >> 4;
    int sub  = lane & 15;

    int beg = g_rowptr_v[v];
    int end = g_rowptr_v[v + 1];
    const uint4* Zh4 = reinterpret_cast<const uint4*>(g_Zh);

    float acc[8];
#pragma unroll
    for (int j = 0; j < 8; j++) acc[j] = 0.f;

    int i = beg + half;
    for (; i + 6 < end; i += 8) {
        int d0 = (int)__ldg(&g_dst_by_v[i + 0]);
        int d1 = (int)__ldg(&g_dst_by_v[i + 2]);
        int d2 = (int)__ldg(&g_dst_by_v[i + 4]);
        int d3 = (int)__ldg(&g_dst_by_v[i + 6]);
        uint4 u0 = __ldg(&Zh4[(size_t)d0 * 16 + sub]);
        uint4 u1 = __ldg(&Zh4[(size_t)d1 * 16 + sub]);
        uint4 u2 = __ldg(&Zh4[(size_t)d2 * 16 + sub]);
        uint4 u3 = __ldg(&Zh4[(size_t)d3 * 16 + sub]);
#pragma unroll
        for (int j = 0; j < 4; j++) {
            uint4 u = (j == 0) ? u0 : (j == 1) ? u1 : (j == 2) ? u2 : u3;
            const __half2* h = reinterpret_cast<const __half2*>(&u);
#pragma unroll
            for (int q = 0; q < 4; q++) {
                float2 f = __half22float2(h[q]);
                acc[q * 2]     += f.x;
                acc[q * 2 + 1] += f.y;
            }
        }
    }
    for (; i < end; i += 2) {
        int d = (int)__ldg(&g_dst_by_v[i]);
        uint4 u = __ldg(&Zh4[(size_t)d * 16 + sub]);
        const __half2* h = reinterpret_cast<const __half2*>(&u);
#pragma unroll
        for (int q = 0; q < 4; q++) {
            float2 f = __half22float2(h[q]);
            acc[q * 2]     += f.x;
            acc[q * 2 + 1] += f.y;
        }
    }

#pragma unroll
    for (int j = 0; j < 8; j++)
        acc[j] += __shfl_xor_sync(0xffffffffu, acc[j], 16);

    if (half == 0) {
        float sc = degV[v];
        float* o = out + (size_t)v * CH + sub * 8;
        *reinterpret_cast<float4*>(o) =
            make_float4(acc[0] * sc, acc[1] * sc, acc[2] * sc, acc[3] * sc);
        *reinterpret_cast<float4*>(o + 4) =
            make_float4(acc[4] * sc, acc[5] * sc, acc[6] * sc, acc[7] * sc);
    }
}

// ---------------------------------------------------------------------------
// Launch (round-10 schedule, unchanged)
// ---------------------------------------------------------------------------
extern "C" void kernel_launch(void* const* d_in, const int* in_sizes, int n_in,
                              void* d_out, int out_size) {
    const float* X    = (const float*)d_in[0];
    const float* Wlin = (const float*)d_in[1];
    const float* degE = (const float*)d_in[2];
    const float* degV = (const float*)d_in[3];
    const float* Wbuf = (const float*)d_in[4];
    const int*   src  = (const int*)d_in[5];
    const int*   dst  = (const int*)d_in[6];
    float*       out  = (float*)d_out;

    static cudaStream_t s1 = nullptr, s2 = nullptr;
    static cudaEvent_t evFork = nullptr, evX = nullptr, evV = nullptr, evH = nullptr;
    if (!s1) {
        cudaStreamCreateWithFlags(&s1, cudaStreamNonBlocking);
        cudaStreamCreateWithFlags(&s2, cudaStreamNonBlocking);
        cudaEventCreateWithFlags(&evFork, cudaEventDisableTiming);
        cudaEventCreateWithFlags(&evX,    cudaEventDisableTiming);
        cudaEventCreateWithFlags(&evV,    cudaEventDisableTiming);
        cudaEventCreateWithFlags(&evH,    cudaEventDisableTiming);
    }

    int *p_cnt_e, *p_cnt_v, *p_sync_e, *p_sync_v;
    int *p_rowptr_e, *p_rowptr_v;
    int *p_part_e, *p_boff_e, *p_part_v, *p_boff_v;
    cudaGetSymbolAddress((void**)&p_cnt_e,    g_cnt_e);
    cudaGetSymbolAddress((void**)&p_cnt_v,    g_cnt_v);
    cudaGetSymbolAddress((void**)&p_sync_e,   g_sync_e);
    cudaGetSymbolAddress((void**)&p_sync_v,   g_sync_v);
    cudaGetSymbolAddress((void**)&p_rowptr_e, g_rowptr_e);
    cudaGetSymbolAddress((void**)&p_rowptr_v, g_rowptr_v);
    cudaGetSymbolAddress((void**)&p_part_e,   g_part_e);
    cudaGetSymbolAddress((void**)&p_boff_e,   g_boff_e);
    cudaGetSymbolAddress((void**)&p_part_v,   g_part_v);
    cudaGetSymbolAddress((void**)&p_boff_v,   g_boff_v);

    cudaFuncSetAttribute(gemm_hmma_kernel,
                         cudaFuncAttributeMaxDynamicSharedMemorySize, 69632);

    const int nEdgeBlk4 = (NNZ / 4 + 255) / 256;
    const int nEdgeBlk8 = (NNZ / 8 + 255) / 256;

    // fork
    cudaEventRecord(evFork, 0);
    cudaStreamWaitEvent(s1, evFork, 0);
    cudaStreamWaitEvent(s2, evFork, 0);

    // s1: fp16 converts (hidden under hist)
    {
        size_t nThreads = (size_t)N_NODES * CH / 8 + (size_t)CH * CH / 8;
        convertAll_kernel<<<(int)((nThreads + 255) / 256), 256, 0, s1>>>(X, Wlin);
    }
    cudaEventRecord(evX, s1);

    // main: zero counters, then the single atomic pass (hist + rank tickets)
    cudaMemsetAsync(p_cnt_e, 0, N_HEDGES * sizeof(int));
    cudaMemsetAsync(p_cnt_v, 0, N_NODES  * sizeof(int));
    cudaMemsetAsync(p_sync_e, 0, 2 * sizeof(int));
    cudaMemsetAsync(p_sync_v, 0, 2 * sizeof(int));
    hist_kernel<<<nEdgeBlk8, 256>>>((const int4*)src, (const int4*)dst);
    cudaEventRecord(evH, 0);

    // s2: V-side scan + place (atomic-free) concurrent with E-side
    cudaStreamWaitEvent(s2, evH, 0);
    scan_kernel<<<NB_V, 1024, 0, s2>>>(p_cnt_v, N_NODES, p_rowptr_v,
                                       p_part_v, p_boff_v, p_sync_v, NB_V);
    placeV_kernel<<<nEdgeBlk4, 256, 0, s2>>>((const int4*)src, (const int4*)dst);
    cudaEventRecord(evV, s2);

    // main: E-side scan + place (atomic-free)
    scan_kernel<<<NB_E, 1024>>>(p_cnt_e, N_HEDGES, p_rowptr_e,
                                p_part_e, p_boff_e, p_sync_e, NB_E);
    placeE_kernel<<<nEdgeBlk4, 256>>>((const int4*)src, (const int4*)dst);

    // main: seg1 -> gemm -> seg2
    cudaStreamWaitEvent(0, evX, 0);
    seg1_kernel<<<(N_HEDGES * 32 + 255) / 256, 256>>>(degE, Wbuf);
    gemm_hmma_kernel<<<(N_HEDGES + 127) / 128, 256, 69632>>>();

    cudaStreamWaitEvent(0, evV, 0);
    seg2_kernel<<<(N_NODES * 32 + 255) / 256, 256>>>(degV, out);
}

// round 12
// speedup vs baseline: 1.0759x; 1.0759x over previous
#include <cuda_runtime.h>
#include <cuda_fp16.h>
#include <cstdint>

#define N_NODES  100000
#define N_HEDGES 25000
#define NNZ      1600000
#define CH       128

#define NB_E ((N_HEDGES + 1023) / 1024)   // 25
#define NB_V ((N_NODES  + 1023) / 1024)   // 98

// ---------------------------------------------------------------------------
// Device-global scratch
// ---------------------------------------------------------------------------
__device__ __half g_Xh[(size_t)N_NODES * CH];   // fp16 X            (25.6 MB)
__device__ __half g_Wh[CH * CH];                // fp16 Wlin
__device__ __half g_Yh[(size_t)N_HEDGES * CH];  // fp16 seg1 output  ( 6.4 MB)
__device__ __half g_Zh[(size_t)N_HEDGES * CH];  // fp16 GEMM output  ( 6.4 MB)

__device__ int g_cnt_e[N_HEDGES];
__device__ int g_cnt_v[N_NODES];
__device__ int g_rowptr_e[N_HEDGES + 1];
__device__ int g_rowptr_v[N_NODES + 1];
__device__ unsigned short g_rank_e[NNZ];   // ticket of edge within its dst segment
__device__ unsigned short g_rank_v[NNZ];   // ticket of edge within its src segment
__device__ int g_src_by_e[NNZ];
__device__ int g_dst_by_v[NNZ];
__device__ int g_part_e[128];
__device__ int g_boff_e[128];
__device__ int g_part_v[128];
__device__ int g_boff_v[128];
__device__ int g_sync_e[2];
__device__ int g_sync_v[2];

// ---------------------------------------------------------------------------
// fp32 -> fp16 convert: X and Wlin in one launch
// ---------------------------------------------------------------------------
__global__ __launch_bounds__(256) void convertAll_kernel(const float* __restrict__ X,
                                                         const float* __restrict__ W) {
    const size_t nX8 = (size_t)N_NODES * CH / 8;
    const size_t nW8 = (size_t)CH * CH / 8;
    size_t t = (size_t)blockIdx.x * blockDim.x + threadIdx.x;
    const float* srcp;
    __half* dstp;
    size_t i;
    if (t < nX8) { srcp = X; dstp = g_Xh; i = t * 8; }
    else if (t < nX8 + nW8) { srcp = W; dstp = g_Wh; i = (t - nX8) * 8; }
    else return;
    float4 a = *reinterpret_cast<const float4*>(srcp + i);
    float4 b = *reinterpret_cast<const float4*>(srcp + i + 4);
    __half2 h[4];
    h[0] = __floats2half2_rn(a.x, a.y);
    h[1] = __floats2half2_rn(a.z, a.w);
    h[2] = __floats2half2_rn(b.x, b.y);
    h[3] = __floats2half2_rn(b.z, b.w);
    *reinterpret_cast<uint4*>(dstp + i) = *reinterpret_cast<uint4*>(h);
}

// ---------------------------------------------------------------------------
// Per-side histogram + rank tickets (4 edges / thread).
// histE is on the critical path; histV runs later on s2.
// ---------------------------------------------------------------------------
__global__ void histE_kernel(const int4* __restrict__ dst4) {
    int i = blockIdx.x * blockDim.x + threadIdx.x;
    if (i >= NNZ / 4) return;
    int4 d = __ldg(&dst4[i]);
    unsigned short re[4];
    re[0] = (unsigned short)atomicAdd(&g_cnt_e[d.x], 1);
    re[1] = (unsigned short)atomicAdd(&g_cnt_e[d.y], 1);
    re[2] = (unsigned short)atomicAdd(&g_cnt_e[d.z], 1);
    re[3] = (unsigned short)atomicAdd(&g_cnt_e[d.w], 1);
    *reinterpret_cast<ushort4*>(g_rank_e + i * 4) = make_ushort4(re[0], re[1], re[2], re[3]);
}

__global__ void histV_kernel(const int4* __restrict__ src4) {
    int i = blockIdx.x * blockDim.x + threadIdx.x;
    if (i >= NNZ / 4) return;
    int4 s = __ldg(&src4[i]);
    unsigned short rv[4];
    rv[0] = (unsigned short)atomicAdd(&g_cnt_v[s.x], 1);
    rv[1] = (unsigned short)atomicAdd(&g_cnt_v[s.y], 1);
    rv[2] = (unsigned short)atomicAdd(&g_cnt_v[s.z], 1);
    rv[3] = (unsigned short)atomicAdd(&g_cnt_v[s.w], 1);
    *reinterpret_cast<ushort4*>(g_rank_v + i * 4) = make_ushort4(rv[0], rv[1], rv[2], rv[3]);
}

// ---------------------------------------------------------------------------
// One-pass scan (per side). nblk blocks, all resident.
// ---------------------------------------------------------------------------
__global__ __launch_bounds__(1024) void scan_kernel(const int* __restrict__ cnt, int n,
                                                    int* __restrict__ rowptr,
                                                    int* __restrict__ part,
                                                    int* __restrict__ boff,
                                                    int* __restrict__ sync, int nblk) {
    __shared__ int warpsum[32];
    __shared__ int p[128];
    __shared__ int sh_flag;
    __shared__ int sh_boff;

    const int tid  = threadIdx.x;
    const int bid  = blockIdx.x;
    const int i    = bid * 1024 + tid;
    const int v0   = (i < n) ? cnt[i] : 0;
    const int lane = tid & 31;
    const int warp = tid >> 5;

    int x = v0;
#pragma unroll
    for (int o = 1; o < 32; o <<= 1) {
        int y = __shfl_up_sync(0xffffffffu, x, o);
        if (lane >= o) x += y;
    }
    if (lane == 31) warpsum[warp] = x;
    __syncthreads();
    if (warp == 0) {
        int w = warpsum[lane];
#pragma unroll
        for (int o = 1; o < 32; o <<= 1) {
            int y = __shfl_up_sync(0xffffffffu, w, o);
            if (lane >= o) w += y;
        }
        warpsum[lane] = w;
    }
    __syncthreads();
    const int incl = x + (warp ? warpsum[warp - 1] : 0);

    if (tid == 1023) {
        part[bid] = incl;
        __threadfence();
        int ticket = atomicAdd(&sync[0], 1);
        sh_flag = (ticket == nblk - 1);
    }
    __syncthreads();

    if (sh_flag) {
        int mine = 0;
        if (tid < nblk) {
            mine = atomicAdd(&part[tid], 0);
            p[tid] = mine;
        }
        __syncthreads();
#pragma unroll
        for (int o = 1; o < 128; o <<= 1) {
            int add = (tid < nblk && tid >= o) ? p[tid - o] : 0;
            __syncthreads();
            if (tid < nblk) p[tid] += add;
            __syncthreads();
        }
        if (tid < nblk) boff[tid] = p[tid] - mine;
        if (tid == nblk - 1) rowptr[n] = p[tid];
        __threadfence();
        if (tid == 0) atomicExch(&sync[1], 1);
    }

    if (tid == 0) {
        while (atomicAdd(&sync[1], 0) == 0) __nanosleep(64);
        sh_boff = atomicAdd(&boff[bid], 0);
    }
    __syncthreads();

    if (i < n) rowptr[i] = incl - v0 + sh_boff;
}

// ---------------------------------------------------------------------------
// ATOMIC-FREE placement: pos = rowptr[seg] + rank  (4 edges / thread)
// ---------------------------------------------------------------------------
__global__ void placeE_kernel(const int4* __restrict__ src4, const int4* __restrict__ dst4) {
    int i = blockIdx.x * blockDim.x + threadIdx.x;
    if (i >= NNZ / 4) return;
    int4 s = __ldg(&src4[i]);
    int4 d = __ldg(&dst4[i]);
    ushort4 r = *reinterpret_cast<const ushort4*>(g_rank_e + i * 4);
    g_src_by_e[__ldg(&g_rowptr_e[d.x]) + r.x] = s.x;
    g_src_by_e[__ldg(&g_rowptr_e[d.y]) + r.y] = s.y;
    g_src_by_e[__ldg(&g_rowptr_e[d.z]) + r.z] = s.z;
    g_src_by_e[__ldg(&g_rowptr_e[d.w]) + r.w] = s.w;
}

__global__ void placeV_kernel(const int4* __restrict__ src4, const int4* __restrict__ dst4) {
    int i = blockIdx.x * blockDim.x + threadIdx.x;
    if (i >= NNZ / 4) return;
    int4 s = __ldg(&src4[i]);
    int4 d = __ldg(&dst4[i]);
    ushort4 r = *reinterpret_cast<const ushort4*>(g_rank_v + i * 4);
    g_dst_by_v[__ldg(&g_rowptr_v[s.x]) + r.x] = d.x;
    g_dst_by_v[__ldg(&g_rowptr_v[s.y]) + r.y] = d.y;
    g_dst_by_v[__ldg(&g_rowptr_v[s.z]) + r.z] = d.z;
    g_dst_by_v[__ldg(&g_rowptr_v[s.w]) + r.w] = d.w;
}

// ---------------------------------------------------------------------------
// Stage 1: warp per hyperedge (16 lanes x uint4, warp-halves alternate edges)
// ---------------------------------------------------------------------------
__global__ __launch_bounds__(256) void seg1_kernel(const float* __restrict__ degE,
                                                   const float* __restrict__ Wbuf) {
    int gid  = blockIdx.x * blockDim.x + threadIdx.x;
    int e    = gid >> 5;
    int lane = gid & 31;
    if (e >= N_HEDGES) return;
    int half = lane >> 4;
    int sub  = lane & 15;

    int beg = g_rowptr_e[e];
    int end = g_rowptr_e[e + 1];
    const uint4* Xh4 = reinterpret_cast<const uint4*>(g_Xh);

    float acc[8];
#pragma unroll
    for (int j = 0; j < 8; j++) acc[j] = 0.f;

    int i = beg + half;
    for (; i + 6 < end; i += 8) {
        int s0 = __ldg(&g_src_by_e[i + 0]);
        int s1 = __ldg(&g_src_by_e[i + 2]);
        int s2 = __ldg(&g_src_by_e[i + 4]);
        int s3 = __ldg(&g_src_by_e[i + 6]);
        uint4 u0 = __ldg(&Xh4[(size_t)s0 * 16 + sub]);
        uint4 u1 = __ldg(&Xh4[(size_t)s1 * 16 + sub]);
        uint4 u2 = __ldg(&Xh4[(size_t)s2 * 16 + sub]);
        uint4 u3 = __ldg(&Xh4[(size_t)s3 * 16 + sub]);
#pragma unroll
        for (int j = 0; j < 4; j++) {
            uint4 u = (j == 0) ? u0 : (j == 1) ? u1 : (j == 2) ? u2 : u3;
            const __half2* h = reinterpret_cast<const __half2*>(&u);
#pragma unroll
            for (int q = 0; q < 4; q++) {
                float2 f = __half22float2(h[q]);
                acc[q * 2]     += f.x;
                acc[q * 2 + 1] += f.y;
            }
        }
    }
    for (; i < end; i += 2) {
        int s = __ldg(&g_src_by_e[i]);
        uint4 u = __ldg(&Xh4[(size_t)s * 16 + sub]);
        const __half2* h = reinterpret_cast<const __half2*>(&u);
#pragma unroll
        for (int q = 0; q < 4; q++) {
            float2 f = __half22float2(h[q]);
            acc[q * 2]     += f.x;
            acc[q * 2 + 1] += f.y;
        }
    }

#pragma unroll
    for (int j = 0; j < 8; j++)
        acc[j] += __shfl_xor_sync(0xffffffffu, acc[j], 16);

    if (half == 0) {
        float sc = degE[e] * Wbuf[e];
        __half2 h[4];
#pragma unroll
        for (int q = 0; q < 4; q++)
            h[q] = __floats2half2_rn(acc[q * 2] * sc, acc[q * 2 + 1] * sc);
        *reinterpret_cast<uint4*>(g_Yh + (size_t)e * CH + sub * 8) =
            *reinterpret_cast<uint4*>(h);
    }
}

// ---------------------------------------------------------------------------
// HMMA GEMM: Zh = Yh @ Wh (fp16 in, fp32 accum, fp16 out)
// ---------------------------------------------------------------------------
#define GS 136

__global__ __launch_bounds__(256) void gemm_hmma_kernel() {
    extern __shared__ __half dsm[];
    __half* As = dsm;
    __half* Bs = dsm + 128 * GS;

    const int tid  = threadIdx.x;
    const int warp = tid >> 5;
    const int lane = tid & 31;
    const int row0 = blockIdx.x * 128;

    for (int t = tid; t < 128 * 16; t += 256) {
        int r = t >> 4;
        int c = (t & 15) * 8;
        uint4 v = make_uint4(0, 0, 0, 0);
        if (row0 + r < N_HEDGES)
            v = *reinterpret_cast<const uint4*>(g_Yh + (size_t)(row0 + r) * CH + c);
        *reinterpret_cast<uint4*>(&As[r * GS + c]) = v;
        *reinterpret_cast<uint4*>(&Bs[r * GS + c]) =
            *reinterpret_cast<const uint4*>(g_Wh + (size_t)r * CH + c);
    }
    __syncthreads();

    const int m0 = warp * 16;
    float acc[16][4];
#pragma unroll
    for (int t = 0; t < 16; t++)
#pragma unroll
        for (int j = 0; j < 4; j++) acc[t][j] = 0.f;

#pragma unroll
    for (int k0 = 0; k0 < 128; k0 += 16) {
        uint32_t a[4];
        {
            uint32_t addr = (uint32_t)__cvta_generic_to_shared(
                &As[(m0 + (lane & 15)) * GS + k0 + (lane >> 4) * 8]);
            asm volatile("ldmatrix.sync.aligned.m8n8.x4.shared.b16 {%0,%1,%2,%3}, [%4];"
                         : "=r"(a[0]), "=r"(a[1]), "=r"(a[2]), "=r"(a[3]) : "r"(addr));
        }
#pragma unroll
        for (int n0 = 0; n0 < 128; n0 += 16) {
            uint32_t b[4];
            uint32_t addr = (uint32_t)__cvta_generic_to_shared(
                &Bs[(k0 + (lane & 15)) * GS + n0 + (lane >> 4) * 8]);
            asm volatile("ldmatrix.sync.aligned.m8n8.x4.trans.shared.b16 {%0,%1,%2,%3}, [%4];"
                         : "=r"(b[0]), "=r"(b[1]), "=r"(b[2]), "=r"(b[3]) : "r"(addr));
            int t0 = n0 >> 3;
            asm volatile("mma.sync.aligned.m16n8k16.row.col.f32.f16.f16.f32 "
                         "{%0,%1,%2,%3},{%4,%5,%6,%7},{%8,%9},{%0,%1,%2,%3};"
                         : "+f"(acc[t0][0]), "+f"(acc[t0][1]), "+f"(acc[t0][2]), "+f"(acc[t0][3])
                         : "r"(a[0]), "r"(a[1]), "r"(a[2]), "r"(a[3]), "r"(b[0]), "r"(b[1]));
            asm volatile("mma.sync.aligned.m16n8k16.row.col.f32.f16.f16.f32 "
                         "{%0,%1,%2,%3},{%4,%5,%6,%7},{%8,%9},{%0,%1,%2,%3};"
                         : "+f"(acc[t0+1][0]), "+f"(acc[t0+1][1]), "+f"(acc[t0+1][2]), "+f"(acc[t0+1][3])
                         : "r"(a[0]), "r"(a[1]), "r"(a[2]), "r"(a[3]), "r"(b[2]), "r"(b[3]));
        }
    }

    const int groupID = lane >> 2;
    const int tig     = lane & 3;
    const int rowA = row0 + m0 + groupID;
    const int rowB = rowA + 8;
#pragma unroll
    for (int t = 0; t < 16; t++) {
        int col = t * 8 + tig * 2;
        if (rowA < N_HEDGES)
            *reinterpret_cast<__half2*>(g_Zh + (size_t)rowA * CH + col) =
                __floats2half2_rn(acc[t][0], acc[t][1]);
        if (rowB < N_HEDGES)
            *reinterpret_cast<__half2*>(g_Zh + (size_t)rowB * CH + col) =
                __floats2half2_rn(acc[t][2], acc[t][3]);
    }
}

// ---------------------------------------------------------------------------
// Stage 2: warp per node (round-10 layout)
// ---------------------------------------------------------------------------
__global__ __launch_bounds__(256) void seg2_kernel(const float* __restrict__ degV,
                                                   float* __restrict__ out) {
    int gid  = blockIdx.x * blockDim.x + threadIdx.x;
    int v    = gid >> 5;
    int lane = gid & 31;
    if (v >= N_NODES) return;
    int half = lane >> 4;
    int sub  = lane & 15;

    int beg = g_rowptr_v[v];
    int end = g_rowptr_v[v + 1];
    const uint4* Zh4 = reinterpret_cast<const uint4*>(g_Zh);

    float acc[8];
#pragma unroll
    for (int j = 0; j < 8; j++) acc[j] = 0.f;

    int i = beg + half;
    for (; i + 2 < end; i += 4) {
        int d0 = __ldg(&g_dst_by_v[i + 0]);
        int d1 = __ldg(&g_dst_by_v[i + 2]);
        uint4 u0 = __ldg(&Zh4[(size_t)d0 * 16 + sub]);
        uint4 u1 = __ldg(&Zh4[(size_t)d1 * 16 + sub]);
#pragma unroll
        for (int j = 0; j < 2; j++) {
            uint4 u = (j == 0) ? u0 : u1;
            const __half2* h = reinterpret_cast<const __half2*>(&u);
#pragma unroll
            for (int q = 0; q < 4; q++) {
                float2 f = __half22float2(h[q]);
                acc[q * 2]     += f.x;
                acc[q * 2 + 1] += f.y;
            }
        }
    }
    for (; i < end; i += 2) {
        int d = __ldg(&g_dst_by_v[i]);
        uint4 u = __ldg(&Zh4[(size_t)d * 16 + sub]);
        const __half2* h = reinterpret_cast<const __half2*>(&u);
#pragma unroll
        for (int q = 0; q < 4; q++) {
            float2 f = __half22float2(h[q]);
            acc[q * 2]     += f.x;
            acc[q * 2 + 1] += f.y;
        }
    }

#pragma unroll
    for (int j = 0; j < 8; j++)
        acc[j] += __shfl_xor_sync(0xffffffffu, acc[j], 16);

    if (half == 0) {
        float sc = degV[v];
        float* o = out + (size_t)v * CH + sub * 8;
        *reinterpret_cast<float4*>(o) =
            make_float4(acc[0] * sc, acc[1] * sc, acc[2] * sc, acc[3] * sc);
        *reinterpret_cast<float4*>(o + 4) =
            make_float4(acc[4] * sc, acc[5] * sc, acc[6] * sc, acc[7] * sc);
    }
}

// ---------------------------------------------------------------------------
// Launch: histE alone on main (critical); V-chain (histV->scanV->placeV) on s2
// after histE, overlapping scanE/placeE/seg1/gemm; converts on s1 under histE.
// ---------------------------------------------------------------------------
extern "C" void kernel_launch(void* const* d_in, const int* in_sizes, int n_in,
                              void* d_out, int out_size) {
    const float* X    = (const float*)d_in[0];
    const float* Wlin = (const float*)d_in[1];
    const float* degE = (const float*)d_in[2];
    const float* degV = (const float*)d_in[3];
    const float* Wbuf = (const float*)d_in[4];
    const int*   src  = (const int*)d_in[5];
    const int*   dst  = (const int*)d_in[6];
    float*       out  = (float*)d_out;

    static cudaStream_t s1 = nullptr, s2 = nullptr;
    static cudaEvent_t evFork = nullptr, evX = nullptr, evV = nullptr, evHE = nullptr;
    if (!s1) {
        cudaStreamCreateWithFlags(&s1, cudaStreamNonBlocking);
        cudaStreamCreateWithFlags(&s2, cudaStreamNonBlocking);
        cudaEventCreateWithFlags(&evFork, cudaEventDisableTiming);
        cudaEventCreateWithFlags(&evX,    cudaEventDisableTiming);
        cudaEventCreateWithFlags(&evV,    cudaEventDisableTiming);
        cudaEventCreateWithFlags(&evHE,   cudaEventDisableTiming);
    }

    int *p_cnt_e, *p_cnt_v, *p_sync_e, *p_sync_v;
    int *p_rowptr_e, *p_rowptr_v;
    int *p_part_e, *p_boff_e, *p_part_v, *p_boff_v;
    cudaGetSymbolAddress((void**)&p_cnt_e,    g_cnt_e);
    cudaGetSymbolAddress((void**)&p_cnt_v,    g_cnt_v);
    cudaGetSymbolAddress((void**)&p_sync_e,   g_sync_e);
    cudaGetSymbolAddress((void**)&p_sync_v,   g_sync_v);
    cudaGetSymbolAddress((void**)&p_rowptr_e, g_rowptr_e);
    cudaGetSymbolAddress((void**)&p_rowptr_v, g_rowptr_v);
    cudaGetSymbolAddress((void**)&p_part_e,   g_part_e);
    cudaGetSymbolAddress((void**)&p_boff_e,   g_boff_e);
    cudaGetSymbolAddress((void**)&p_part_v,   g_part_v);
    cudaGetSymbolAddress((void**)&p_boff_v,   g_boff_v);

    cudaFuncSetAttribute(gemm_hmma_kernel,
                         cudaFuncAttributeMaxDynamicSharedMemorySize, 69632);

    const int nEdgeBlk = (NNZ / 4 + 255) / 256;

    // fork
    cudaEventRecord(evFork, 0);
    cudaStreamWaitEvent(s1, evFork, 0);
    cudaStreamWaitEvent(s2, evFork, 0);

    // s1: fp16 converts (hidden under histE)
    {
        size_t nThreads = (size_t)N_NODES * CH / 8 + (size_t)CH * CH / 8;
        convertAll_kernel<<<(int)((nThreads + 255) / 256), 256, 0, s1>>>(X, Wlin);
    }
    cudaEventRecord(evX, s1);

    // s2: V-side counter memsets at fork (pure writes, harmless under histE)
    cudaMemsetAsync(p_cnt_v, 0, N_NODES * sizeof(int), s2);
    cudaMemsetAsync(p_sync_v, 0, 2 * sizeof(int), s2);

    // main: E-side memsets + histE — the only atomic pass on the critical path
    cudaMemsetAsync(p_cnt_e, 0, N_HEDGES * sizeof(int));
    cudaMemsetAsync(p_sync_e, 0, 2 * sizeof(int));
    histE_kernel<<<nEdgeBlk, 256>>>((const int4*)dst);
    cudaEventRecord(evHE, 0);

    // s2: V-chain AFTER histE (atomics never co-run with atomics);
    // overlaps scanE/placeE/seg1/gemm on main.
    cudaStreamWaitEvent(s2, evHE, 0);
    histV_kernel<<<nEdgeBlk, 256, 0, s2>>>((const int4*)src);
    scan_kernel<<<NB_V, 1024, 0, s2>>>(p_cnt_v, N_NODES, p_rowptr_v,
                                       p_part_v, p_boff_v, p_sync_v, NB_V);
    placeV_kernel<<<nEdgeBlk, 256, 0, s2>>>((const int4*)src, (const int4*)dst);
    cudaEventRecord(evV, s2);

    // main: E-side scan + place (atomic-free), then compute chain
    scan_kernel<<<NB_E, 1024>>>(p_cnt_e, N_HEDGES, p_rowptr_e,
                                p_part_e, p_boff_e, p_sync_e, NB_E);
    placeE_kernel<<<nEdgeBlk, 256>>>((const int4*)src, (const int4*)dst);

    cudaStreamWaitEvent(0, evX, 0);
    seg1_kernel<<<(N_HEDGES * 32 + 255) / 256, 256>>>(degE, Wbuf);
    gemm_hmma_kernel<<<(N_HEDGES + 127) / 128, 256, 69632>>>();

    cudaStreamWaitEvent(0, evV, 0);
    seg2_kernel<<<(N_NODES * 32 + 255) / 256, 256>>>(degV, out);
}

// round 13
// speedup vs baseline: 1.0955x; 1.0181x over previous
#include <cuda_runtime.h>
#include <cuda_fp16.h>
#include <cstdint>

#define N_NODES  100000
#define N_HEDGES 25000
#define NNZ      1600000
#define CH       128

#define NB_E ((N_HEDGES + 1023) / 1024)   // 25
#define NB_V ((N_NODES  + 1023) / 1024)   // 98

// ---------------------------------------------------------------------------
// Device-global scratch (zero-initialized at module load; scan kernels
// re-zero cnt/sync before exiting, so every call sees zeros — no memsets).
// ---------------------------------------------------------------------------
__device__ __half g_Xh[(size_t)N_NODES * CH];   // fp16 X            (25.6 MB)
__device__ __half g_Wh[CH * CH];                // fp16 Wlin
__device__ __half g_Yh[(size_t)N_HEDGES * CH];  // fp16 seg1 output  ( 6.4 MB)
__device__ __half g_Zh[(size_t)N_HEDGES * CH];  // fp16 GEMM output  ( 6.4 MB)

__device__ int g_cnt_e[N_HEDGES];
__device__ int g_cnt_v[N_NODES];
__device__ int g_rowptr_e[N_HEDGES + 1];
__device__ int g_rowptr_v[N_NODES + 1];
__device__ unsigned short g_rank_e[NNZ];   // ticket of edge within its dst segment
__device__ unsigned short g_rank_v[NNZ];   // ticket of edge within its src segment
__device__ int g_src_by_e[NNZ];
__device__ int g_dst_by_v[NNZ];
__device__ int g_part_e[128];
__device__ int g_boff_e[128];
__device__ int g_part_v[128];
__device__ int g_boff_v[128];
__device__ int g_sync_e[2];
__device__ int g_sync_v[2];

// ---------------------------------------------------------------------------
// fp32 -> fp16 convert: X and Wlin in one launch
// ---------------------------------------------------------------------------
__global__ __launch_bounds__(256) void convertAll_kernel(const float* __restrict__ X,
                                                         const float* __restrict__ W) {
    const size_t nX8 = (size_t)N_NODES * CH / 8;
    const size_t nW8 = (size_t)CH * CH / 8;
    size_t t = (size_t)blockIdx.x * blockDim.x + threadIdx.x;
    const float* srcp;
    __half* dstp;
    size_t i;
    if (t < nX8) { srcp = X; dstp = g_Xh; i = t * 8; }
    else if (t < nX8 + nW8) { srcp = W; dstp = g_Wh; i = (t - nX8) * 8; }
    else return;
    float4 a = *reinterpret_cast<const float4*>(srcp + i);
    float4 b = *reinterpret_cast<const float4*>(srcp + i + 4);
    __half2 h[4];
    h[0] = __floats2half2_rn(a.x, a.y);
    h[1] = __floats2half2_rn(a.z, a.w);
    h[2] = __floats2half2_rn(b.x, b.y);
    h[3] = __floats2half2_rn(b.z, b.w);
    *reinterpret_cast<uint4*>(dstp + i) = *reinterpret_cast<uint4*>(h);
}

// ---------------------------------------------------------------------------
// Per-side histogram + rank tickets (4 edges / thread).
// Requires cnt[] == 0 on entry (guaranteed by load-time zero-init on the
// first call and by scan_kernel's self-clean on every subsequent call).
// ---------------------------------------------------------------------------
__global__ void histE_kernel(const int4* __restrict__ dst4) {
    int i = blockIdx.x * blockDim.x + threadIdx.x;
    if (i >= NNZ / 4) return;
    int4 d = __ldg(&dst4[i]);
    unsigned short re[4];
    re[0] = (unsigned short)atomicAdd(&g_cnt_e[d.x], 1);
    re[1] = (unsigned short)atomicAdd(&g_cnt_e[d.y], 1);
    re[2] = (unsigned short)atomicAdd(&g_cnt_e[d.z], 1);
    re[3] = (unsigned short)atomicAdd(&g_cnt_e[d.w], 1);
    *reinterpret_cast<ushort4*>(g_rank_e + i * 4) = make_ushort4(re[0], re[1], re[2], re[3]);
}

__global__ void histV_kernel(const int4* __restrict__ src4) {
    int i = blockIdx.x * blockDim.x + threadIdx.x;
    if (i >= NNZ / 4) return;
    int4 s = __ldg(&src4[i]);
    unsigned short rv[4];
    rv[0] = (unsigned short)atomicAdd(&g_cnt_v[s.x], 1);
    rv[1] = (unsigned short)atomicAdd(&g_cnt_v[s.y], 1);
    rv[2] = (unsigned short)atomicAdd(&g_cnt_v[s.z], 1);
    rv[3] = (unsigned short)atomicAdd(&g_cnt_v[s.w], 1);
    *reinterpret_cast<ushort4*>(g_rank_v + i * 4) = make_ushort4(rv[0], rv[1], rv[2], rv[3]);
}

// ---------------------------------------------------------------------------
// One-pass scan (per side). nblk blocks, all resident.
// SELF-CLEANING: zeroes cnt[i] after reading; the last block to exit resets
// the sync pair, so the next call starts from the zeroed state.
// ---------------------------------------------------------------------------
__global__ __launch_bounds__(1024) void scan_kernel(int* __restrict__ cnt, int n,
                                                    int* __restrict__ rowptr,
                                                    int* __restrict__ part,
                                                    int* __restrict__ boff,
                                                    int* __restrict__ sync, int nblk) {
    __shared__ int warpsum[32];
    __shared__ int p[128];
    __shared__ int sh_flag;
    __shared__ int sh_boff;

    const int tid  = threadIdx.x;
    const int bid  = blockIdx.x;
    const int i    = bid * 1024 + tid;
    const int v0   = (i < n) ? cnt[i] : 0;
    if (i < n) cnt[i] = 0;                 // self-clean (each i touched once)
    const int lane = tid & 31;
    const int warp = tid >> 5;

    int x = v0;
#pragma unroll
    for (int o = 1; o < 32; o <<= 1) {
        int y = __shfl_up_sync(0xffffffffu, x, o);
        if (lane >= o) x += y;
    }
    if (lane == 31) warpsum[warp] = x;
    __syncthreads();
    if (warp == 0) {
        int w = warpsum[lane];
#pragma unroll
        for (int o = 1; o < 32; o <<= 1) {
            int y = __shfl_up_sync(0xffffffffu, w, o);
            if (lane >= o) w += y;
        }
        warpsum[lane] = w;
    }
    __syncthreads();
    const int incl = x + (warp ? warpsum[warp - 1] : 0);

    if (tid == 1023) {
        part[bid] = incl;
        __threadfence();
        int ticket = atomicAdd(&sync[0], 1);      // arrival tickets 0..nblk-1
        sh_flag = (ticket == nblk - 1);
    }
    __syncthreads();

    if (sh_flag) {
        int mine = 0;
        if (tid < nblk) {
            mine = atomicAdd(&part[tid], 0);
            p[tid] = mine;
        }
        __syncthreads();
#pragma unroll
        for (int o = 1; o < 128; o <<= 1) {
            int add = (tid < nblk && tid >= o) ? p[tid - o] : 0;
            __syncthreads();
            if (tid < nblk) p[tid] += add;
            __syncthreads();
        }
        if (tid < nblk) boff[tid] = p[tid] - mine;
        if (tid == nblk - 1) rowptr[n] = p[tid];
        __threadfence();
        if (tid == 0) atomicExch(&sync[1], 1);
    }

    if (tid == 0) {
        while (atomicAdd(&sync[1], 0) == 0) __nanosleep(64);
        sh_boff = atomicAdd(&boff[bid], 0);
    }
    __syncthreads();

    if (i < n) rowptr[i] = incl - v0 + sh_boff;

    // exit phase: tickets nblk..2*nblk-1; last exiting block resets sync.
    __syncthreads();
    if (tid == 0) {
        int t2 = atomicAdd(&sync[0], 1);
        if (t2 == 2 * nblk - 1) {
            sync[1] = 0;
            sync[0] = 0;
            __threadfence();
        }
    }
}

// ---------------------------------------------------------------------------
// ATOMIC-FREE placement: pos = rowptr[seg] + rank  (8 edges / thread for MLP)
// ---------------------------------------------------------------------------
__global__ void placeE_kernel(const int4* __restrict__ src4, const int4* __restrict__ dst4) {
    int i = blockIdx.x * blockDim.x + threadIdx.x;
    if (i >= NNZ / 8) return;
    int4 s0 = __ldg(&src4[i * 2 + 0]);
    int4 s1 = __ldg(&src4[i * 2 + 1]);
    int4 d0 = __ldg(&dst4[i * 2 + 0]);
    int4 d1 = __ldg(&dst4[i * 2 + 1]);
    ushort4 r0 = *reinterpret_cast<const ushort4*>(g_rank_e + i * 8);
    ushort4 r1 = *reinterpret_cast<const ushort4*>(g_rank_e + i * 8 + 4);
    int p0 = __ldg(&g_rowptr_e[d0.x]);
    int p1 = __ldg(&g_rowptr_e[d0.y]);
    int p2 = __ldg(&g_rowptr_e[d0.z]);
    int p3 = __ldg(&g_rowptr_e[d0.w]);
    int p4 = __ldg(&g_rowptr_e[d1.x]);
    int p5 = __ldg(&g_rowptr_e[d1.y]);
    int p6 = __ldg(&g_rowptr_e[d1.z]);
    int p7 = __ldg(&g_rowptr_e[d1.w]);
    g_src_by_e[p0 + r0.x] = s0.x;
    g_src_by_e[p1 + r0.y] = s0.y;
    g_src_by_e[p2 + r0.z] = s0.z;
    g_src_by_e[p3 + r0.w] = s0.w;
    g_src_by_e[p4 + r1.x] = s1.x;
    g_src_by_e[p5 + r1.y] = s1.y;
    g_src_by_e[p6 + r1.z] = s1.z;
    g_src_by_e[p7 + r1.w] = s1.w;
}

__global__ void placeV_kernel(const int4* __restrict__ src4, const int4* __restrict__ dst4) {
    int i = blockIdx.x * blockDim.x + threadIdx.x;
    if (i >= NNZ / 8) return;
    int4 s0 = __ldg(&src4[i * 2 + 0]);
    int4 s1 = __ldg(&src4[i * 2 + 1]);
    int4 d0 = __ldg(&dst4[i * 2 + 0]);
    int4 d1 = __ldg(&dst4[i * 2 + 1]);
    ushort4 r0 = *reinterpret_cast<const ushort4*>(g_rank_v + i * 8);
    ushort4 r1 = *reinterpret_cast<const ushort4*>(g_rank_v + i * 8 + 4);
    int p0 = __ldg(&g_rowptr_v[s0.x]);
    int p1 = __ldg(&g_rowptr_v[s0.y]);
    int p2 = __ldg(&g_rowptr_v[s0.z]);
    int p3 = __ldg(&g_rowptr_v[s0.w]);
    int p4 = __ldg(&g_rowptr_v[s1.x]);
    int p5 = __ldg(&g_rowptr_v[s1.y]);
    int p6 = __ldg(&g_rowptr_v[s1.z]);
    int p7 = __ldg(&g_rowptr_v[s1.w]);
    g_dst_by_v[p0 + r0.x] = d0.x;
    g_dst_by_v[p1 + r0.y] = d0.y;
    g_dst_by_v[p2 + r0.z] = d0.z;
    g_dst_by_v[p3 + r0.w] = d0.w;
    g_dst_by_v[p4 + r1.x] = d1.x;
    g_dst_by_v[p5 + r1.y] = d1.y;
    g_dst_by_v[p6 + r1.z] = d1.z;
    g_dst_by_v[p7 + r1.w] = d1.w;
}

// ---------------------------------------------------------------------------
// Stage 1: warp per hyperedge (16 lanes x uint4, warp-halves alternate edges)
// ---------------------------------------------------------------------------
__global__ __launch_bounds__(256) void seg1_kernel(const float* __restrict__ degE,
                                                   const float* __restrict__ Wbuf) {
    int gid  = blockIdx.x * blockDim.x + threadIdx.x;
    int e    = gid >> 5;
    int lane = gid & 31;
    if (e >= N_HEDGES) return;
    int half = lane >> 4;
    int sub  = lane & 15;

    int beg = g_rowptr_e[e];
    int end = g_rowptr_e[e + 1];
    const uint4* Xh4 = reinterpret_cast<const uint4*>(g_Xh);

    float acc[8];
#pragma unroll
    for (int j = 0; j < 8; j++) acc[j] = 0.f;

    int i = beg + half;
    for (; i + 6 < end; i += 8) {
        int s0 = __ldg(&g_src_by_e[i + 0]);
        int s1 = __ldg(&g_src_by_e[i + 2]);
        int s2 = __ldg(&g_src_by_e[i + 4]);
        int s3 = __ldg(&g_src_by_e[i + 6]);
        uint4 u0 = __ldg(&Xh4[(size_t)s0 * 16 + sub]);
        uint4 u1 = __ldg(&Xh4[(size_t)s1 * 16 + sub]);
        uint4 u2 = __ldg(&Xh4[(size_t)s2 * 16 + sub]);
        uint4 u3 = __ldg(&Xh4[(size_t)s3 * 16 + sub]);
#pragma unroll
        for (int j = 0; j < 4; j++) {
            uint4 u = (j == 0) ? u0 : (j == 1) ? u1 : (j == 2) ? u2 : u3;
            const __half2* h = reinterpret_cast<const __half2*>(&u);
#pragma unroll
            for (int q = 0; q < 4; q++) {
                float2 f = __half22float2(h[q]);
                acc[q * 2]     += f.x;
                acc[q * 2 + 1] += f.y;
            }
        }
    }
    for (; i < end; i += 2) {
        int s = __ldg(&g_src_by_e[i]);
        uint4 u = __ldg(&Xh4[(size_t)s * 16 + sub]);
        const __half2* h = reinterpret_cast<const __half2*>(&u);
#pragma unroll
        for (int q = 0; q < 4; q++) {
            float2 f = __half22float2(h[q]);
            acc[q * 2]     += f.x;
            acc[q * 2 + 1] += f.y;
        }
    }

#pragma unroll
    for (int j = 0; j < 8; j++)
        acc[j] += __shfl_xor_sync(0xffffffffu, acc[j], 16);

    if (half == 0) {
        float sc = degE[e] * Wbuf[e];
        __half2 h[4];
#pragma unroll
        for (int q = 0; q < 4; q++)
            h[q] = __floats2half2_rn(acc[q * 2] * sc, acc[q * 2 + 1] * sc);
        *reinterpret_cast<uint4*>(g_Yh + (size_t)e * CH + sub * 8) =
            *reinterpret_cast<uint4*>(h);
    }
}

// ---------------------------------------------------------------------------
// HMMA GEMM: Zh = Yh @ Wh (fp16 in, fp32 accum, fp16 out)
// ---------------------------------------------------------------------------
#define GS 136

__global__ __launch_bounds__(256) void gemm_hmma_kernel() {
    extern __shared__ __half dsm[];
    __half* As = dsm;
    __half* Bs = dsm + 128 * GS;

    const int tid  = threadIdx.x;
    const int warp = tid >> 5;
    const int lane = tid & 31;
    const int row0 = blockIdx.x * 128;

    for (int t = tid; t < 128 * 16; t += 256) {
        int r = t >> 4;
        int c = (t & 15) * 8;
        uint4 v = make_uint4(0, 0, 0, 0);
        if (row0 + r < N_HEDGES)
            v = *reinterpret_cast<const uint4*>(g_Yh + (size_t)(row0 + r) * CH + c);
        *reinterpret_cast<uint4*>(&As[r * GS + c]) = v;
        *reinterpret_cast<uint4*>(&Bs[r * GS + c]) =
            *reinterpret_cast<const uint4*>(g_Wh + (size_t)r * CH + c);
    }
    __syncthreads();

    const int m0 = warp * 16;
    float acc[16][4];
#pragma unroll
    for (int t = 0; t < 16; t++)
#pragma unroll
        for (int j = 0; j < 4; j++) acc[t][j] = 0.f;

#pragma unroll
    for (int k0 = 0; k0 < 128; k0 += 16) {
        uint32_t a[4];
        {
            uint32_t addr = (uint32_t)__cvta_generic_to_shared(
                &As[(m0 + (lane & 15)) * GS + k0 + (lane >> 4) * 8]);
            asm volatile("ldmatrix.sync.aligned.m8n8.x4.shared.b16 {%0,%1,%2,%3}, [%4];"
                         : "=r"(a[0]), "=r"(a[1]), "=r"(a[2]), "=r"(a[3]) : "r"(addr));
        }
#pragma unroll
        for (int n0 = 0; n0 < 128; n0 += 16) {
            uint32_t b[4];
            uint32_t addr = (uint32_t)__cvta_generic_to_shared(
                &Bs[(k0 + (lane & 15)) * GS + n0 + (lane >> 4) * 8]);
            asm volatile("ldmatrix.sync.aligned.m8n8.x4.trans.shared.b16 {%0,%1,%2,%3}, [%4];"
                         : "=r"(b[0]), "=r"(b[1]), "=r"(b[2]), "=r"(b[3]) : "r"(addr));
            int t0 = n0 >> 3;
            asm volatile("mma.sync.aligned.m16n8k16.row.col.f32.f16.f16.f32 "
                         "{%0,%1,%2,%3},{%4,%5,%6,%7},{%8,%9},{%0,%1,%2,%3};"
                         : "+f"(acc[t0][0]), "+f"(acc[t0][1]), "+f"(acc[t0][2]), "+f"(acc[t0][3])
                         : "r"(a[0]), "r"(a[1]), "r"(a[2]), "r"(a[3]), "r"(b[0]), "r"(b[1]));
            asm volatile("mma.sync.aligned.m16n8k16.row.col.f32.f16.f16.f32 "
                         "{%0,%1,%2,%3},{%4,%5,%6,%7},{%8,%9},{%0,%1,%2,%3};"
                         : "+f"(acc[t0+1][0]), "+f"(acc[t0+1][1]), "+f"(acc[t0+1][2]), "+f"(acc[t0+1][3])
                         : "r"(a[0]), "r"(a[1]), "r"(a[2]), "r"(a[3]), "r"(b[2]), "r"(b[3]));
        }
    }

    const int groupID = lane >> 2;
    const int tig     = lane & 3;
    const int rowA = row0 + m0 + groupID;
    const int rowB = rowA + 8;
#pragma unroll
    for (int t = 0; t < 16; t++) {
        int col = t * 8 + tig * 2;
        if (rowA < N_HEDGES)
            *reinterpret_cast<__half2*>(g_Zh + (size_t)rowA * CH + col) =
                __floats2half2_rn(acc[t][0], acc[t][1]);
        if (rowB < N_HEDGES)
            *reinterpret_cast<__half2*>(g_Zh + (size_t)rowB * CH + col) =
                __floats2half2_rn(acc[t][2], acc[t][3]);
    }
}

// ---------------------------------------------------------------------------
// Stage 2: warp per node
// ---------------------------------------------------------------------------
__global__ __launch_bounds__(256) void seg2_kernel(const float* __restrict__ degV,
                                                   float* __restrict__ out) {
    int gid  = blockIdx.x * blockDim.x + threadIdx.x;
    int v    = gid >> 5;
    int lane = gid & 31;
    if (v >= N_NODES) return;
    int half = lane >> 4;
    int sub  = lane & 15;

    int beg = g_rowptr_v[v];
    int end = g_rowptr_v[v + 1];
    const uint4* Zh4 = reinterpret_cast<const uint4*>(g_Zh);

    float acc[8];
#pragma unroll
    for (int j = 0; j < 8; j++) acc[j] = 0.f;

    int i = beg + half;
    for (; i + 2 < end; i += 4) {
        int d0 = __ldg(&g_dst_by_v[i + 0]);
        int d1 = __ldg(&g_dst_by_v[i + 2]);
        uint4 u0 = __ldg(&Zh4[(size_t)d0 * 16 + sub]);
        uint4 u1 = __ldg(&Zh4[(size_t)d1 * 16 + sub]);
#pragma unroll
        for (int j = 0; j < 2; j++) {
            uint4 u = (j == 0) ? u0 : u1;
            const __half2* h = reinterpret_cast<const __half2*>(&u);
#pragma unroll
            for (int q = 0; q < 4; q++) {
                float2 f = __half22float2(h[q]);
                acc[q * 2]     += f.x;
                acc[q * 2 + 1] += f.y;
            }
        }
    }
    for (; i < end; i += 2) {
        int d = __ldg(&g_dst_by_v[i]);
        uint4 u = __ldg(&Zh4[(size_t)d * 16 + sub]);
        const __half2* h = reinterpret_cast<const __half2*>(&u);
#pragma unroll
        for (int q = 0; q < 4; q++) {
            float2 f = __half22float2(h[q]);
            acc[q * 2]     += f.x;
            acc[q * 2 + 1] += f.y;
        }
    }

#pragma unroll
    for (int j = 0; j < 8; j++)
        acc[j] += __shfl_xor_sync(0xffffffffu, acc[j], 16);

    if (half == 0) {
        float sc = degV[v];
        float* o = out + (size_t)v * CH + sub * 8;
        *reinterpret_cast<float4*>(o) =
            make_float4(acc[0] * sc, acc[1] * sc, acc[2] * sc, acc[3] * sc);
        *reinterpret_cast<float4*>(o + 4) =
            make_float4(acc[4] * sc, acc[5] * sc, acc[6] * sc, acc[7] * sc);
    }
}

// ---------------------------------------------------------------------------
// Launch: histE first on main (no memsets — self-cleaning state);
// V-chain on s2 after histE; converts on s1 under histE.
// ---------------------------------------------------------------------------
extern "C" void kernel_launch(void* const* d_in, const int* in_sizes, int n_in,
                              void* d_out, int out_size) {
    const float* X    = (const float*)d_in[0];
    const float* Wlin = (const float*)d_in[1];
    const float* degE = (const float*)d_in[2];
    const float* degV = (const float*)d_in[3];
    const float* Wbuf = (const float*)d_in[4];
    const int*   src  = (const int*)d_in[5];
    const int*   dst  = (const int*)d_in[6];
    float*       out  = (float*)d_out;

    static cudaStream_t s1 = nullptr, s2 = nullptr;
    static cudaEvent_t evFork = nullptr, evX = nullptr, evV = nullptr, evHE = nullptr;
    if (!s1) {
        cudaStreamCreateWithFlags(&s1, cudaStreamNonBlocking);
        cudaStreamCreateWithFlags(&s2, cudaStreamNonBlocking);
        cudaEventCreateWithFlags(&evFork, cudaEventDisableTiming);
        cudaEventCreateWithFlags(&evX,    cudaEventDisableTiming);
        cudaEventCreateWithFlags(&evV,    cudaEventDisableTiming);
        cudaEventCreateWithFlags(&evHE,   cudaEventDisableTiming);
    }

    int *p_cnt_e, *p_cnt_v, *p_sync_e, *p_sync_v;
    int *p_rowptr_e, *p_rowptr_v;
    int *p_part_e, *p_boff_e, *p_part_v, *p_boff_v;
    cudaGetSymbolAddress((void**)&p_cnt_e,    g_cnt_e);
    cudaGetSymbolAddress((void**)&p_cnt_v,    g_cnt_v);
    cudaGetSymbolAddress((void**)&p_sync_e,   g_sync_e);
    cudaGetSymbolAddress((void**)&p_sync_v,   g_sync_v);
    cudaGetSymbolAddress((void**)&p_rowptr_e, g_rowptr_e);
    cudaGetSymbolAddress((void**)&p_rowptr_v, g_rowptr_v);
    cudaGetSymbolAddress((void**)&p_part_e,   g_part_e);
    cudaGetSymbolAddress((void**)&p_boff_e,   g_boff_e);
    cudaGetSymbolAddress((void**)&p_part_v,   g_part_v);
    cudaGetSymbolAddress((void**)&p_boff_v,   g_boff_v);

    cudaFuncSetAttribute(gemm_hmma_kernel,
                         cudaFuncAttributeMaxDynamicSharedMemorySize, 69632);

    const int nEdgeBlk4 = (NNZ / 4 + 255) / 256;
    const int nEdgeBlk8 = (NNZ / 8 + 255) / 256;

    // fork
    cudaEventRecord(evFork, 0);
    cudaStreamWaitEvent(s1, evFork, 0);
    cudaStreamWaitEvent(s2, evFork, 0);

    // s1: fp16 converts (hidden under histE)
    {
        size_t nThreads = (size_t)N_NODES * CH / 8 + (size_t)CH * CH / 8;
        convertAll_kernel<<<(int)((nThreads + 255) / 256), 256, 0, s1>>>(X, Wlin);
    }
    cudaEventRecord(evX, s1);

    // main: histE starts immediately (counters are pre-zeroed by design)
    histE_kernel<<<nEdgeBlk4, 256>>>((const int4*)dst);
    cudaEventRecord(evHE, 0);

    // s2: V-chain AFTER histE (atomics never co-run with atomics);
    // overlaps scanE/placeE/seg1/gemm on main.
    cudaStreamWaitEvent(s2, evHE, 0);
    histV_kernel<<<nEdgeBlk4, 256, 0, s2>>>((const int4*)src);
    scan_kernel<<<NB_V, 1024, 0, s2>>>(p_cnt_v, N_NODES, p_rowptr_v,
                                       p_part_v, p_boff_v, p_sync_v, NB_V);
    placeV_kernel<<<nEdgeBlk8, 256, 0, s2>>>((const int4*)src, (const int4*)dst);
    cudaEventRecord(evV, s2);

    // main: E-side scan + place (atomic-free), then compute chain
    scan_kernel<<<NB_E, 1024>>>(p_cnt_e, N_HEDGES, p_rowptr_e,
                                p_part_e, p_boff_e, p_sync_e, NB_E);
    placeE_kernel<<<nEdgeBlk8, 256>>>((const int4*)src, (const int4*)dst);

    cudaStreamWaitEvent(0, evX, 0);
    seg1_kernel<<<(N_HEDGES * 32 + 255) / 256, 256>>>(degE, Wbuf);
    gemm_hmma_kernel<<<(N_HEDGES + 127) / 128, 256, 69632>>>();

    cudaStreamWaitEvent(0, evV, 0);
    seg2_kernel<<<(N_NODES * 32 + 255) / 256, 256>>>(degV, out);
}

// round 14
// speedup vs baseline: 1.1062x; 1.0098x over previous
#include <cuda_runtime.h>
#include <cuda_fp16.h>
#include <cstdint>

#define N_NODES  100000
#define N_HEDGES 25000
#define NNZ      1600000
#define CH       128

#define NB_E ((N_HEDGES + 1023) / 1024)   // 25
#define NB_V ((N_NODES  + 1023) / 1024)   // 98

// ---------------------------------------------------------------------------
// Device-global scratch (zero-init at load; cnt self-cleaned by scan;
// sync words are MONOTONIC epoch counters — never reset).
// ---------------------------------------------------------------------------
__device__ __half g_Xh[(size_t)N_NODES * CH];   // fp16 X            (25.6 MB)
__device__ __half g_Wh[CH * CH];                // fp16 Wlin
__device__ __half g_Yh[(size_t)N_HEDGES * CH];  // fp16 seg1 output  ( 6.4 MB)
__device__ __half g_Zh[(size_t)N_HEDGES * CH];  // fp16 GEMM output  ( 6.4 MB)

__device__ int g_cnt_e[N_HEDGES];
__device__ int g_cnt_v[N_NODES];
__device__ int g_rowptr_e[N_HEDGES + 1];
__device__ int g_rowptr_v[N_NODES + 1];
__device__ unsigned short g_rank_e[NNZ];   // ticket of edge within its dst segment
__device__ unsigned short g_rank_v[NNZ];   // ticket of edge within its src segment
__device__ int g_src_by_e[NNZ];
__device__ int g_dst_by_v[NNZ];
__device__ int g_part_e[128];
__device__ int g_boff_e[128];
__device__ int g_part_v[128];
__device__ int g_boff_v[128];
__device__ int g_sync_e[2];   // [0]=arrival tickets (monotonic), [1]=release epoch (monotonic)
__device__ int g_sync_v[2];

// ---------------------------------------------------------------------------
// fp32 -> fp16 convert: X and Wlin in one launch
// ---------------------------------------------------------------------------
__global__ __launch_bounds__(256) void convertAll_kernel(const float* __restrict__ X,
                                                         const float* __restrict__ W) {
    const size_t nX8 = (size_t)N_NODES * CH / 8;
    const size_t nW8 = (size_t)CH * CH / 8;
    size_t t = (size_t)blockIdx.x * blockDim.x + threadIdx.x;
    const float* srcp;
    __half* dstp;
    size_t i;
    if (t < nX8) { srcp = X; dstp = g_Xh; i = t * 8; }
    else if (t < nX8 + nW8) { srcp = W; dstp = g_Wh; i = (t - nX8) * 8; }
    else return;
    float4 a = *reinterpret_cast<const float4*>(srcp + i);
    float4 b = *reinterpret_cast<const float4*>(srcp + i + 4);
    __half2 h[4];
    h[0] = __floats2half2_rn(a.x, a.y);
    h[1] = __floats2half2_rn(a.z, a.w);
    h[2] = __floats2half2_rn(b.x, b.y);
    h[3] = __floats2half2_rn(b.z, b.w);
    *reinterpret_cast<uint4*>(dstp + i) = *reinterpret_cast<uint4*>(h);
}

// ---------------------------------------------------------------------------
// Per-side histogram + rank tickets (4 edges / thread).
// Requires cnt[] == 0 on entry (load-time zero-init; scan self-cleans).
// ---------------------------------------------------------------------------
__global__ void histE_kernel(const int4* __restrict__ dst4) {
    int i = blockIdx.x * blockDim.x + threadIdx.x;
    if (i >= NNZ / 4) return;
    int4 d = __ldg(&dst4[i]);
    unsigned short re[4];
    re[0] = (unsigned short)atomicAdd(&g_cnt_e[d.x], 1);
    re[1] = (unsigned short)atomicAdd(&g_cnt_e[d.y], 1);
    re[2] = (unsigned short)atomicAdd(&g_cnt_e[d.z], 1);
    re[3] = (unsigned short)atomicAdd(&g_cnt_e[d.w], 1);
    *reinterpret_cast<ushort4*>(g_rank_e + i * 4) = make_ushort4(re[0], re[1], re[2], re[3]);
}

__global__ void histV_kernel(const int4* __restrict__ src4) {
    int i = blockIdx.x * blockDim.x + threadIdx.x;
    if (i >= NNZ / 4) return;
    int4 s = __ldg(&src4[i]);
    unsigned short rv[4];
    rv[0] = (unsigned short)atomicAdd(&g_cnt_v[s.x], 1);
    rv[1] = (unsigned short)atomicAdd(&g_cnt_v[s.y], 1);
    rv[2] = (unsigned short)atomicAdd(&g_cnt_v[s.z], 1);
    rv[3] = (unsigned short)atomicAdd(&g_cnt_v[s.w], 1);
    *reinterpret_cast<ushort4*>(g_rank_v + i * 4) = make_ushort4(rv[0], rv[1], rv[2], rv[3]);
}

// ---------------------------------------------------------------------------
// One-pass scan (per side), EPOCH-BASED sync (no reset phase):
// - each block snapshots epoch = sync[1] BEFORE arriving (pre-release value)
// - arrival tickets on sync[0] are monotonic; last-of-call = (t+1)%nblk==0
// - release = sync[1]++; waiters spin until sync[1] != epoch
// Self-cleans cnt[]. Deterministic across graph replays.
// ---------------------------------------------------------------------------
__global__ __launch_bounds__(1024) void scan_kernel(int* __restrict__ cnt, int n,
                                                    int* __restrict__ rowptr,
                                                    int* __restrict__ part,
                                                    int* __restrict__ boff,
                                                    int* __restrict__ sync, int nblk) {
    __shared__ int warpsum[32];
    __shared__ int p[128];
    __shared__ int sh_flag;
    __shared__ int sh_boff;
    __shared__ int sh_epoch;

    const int tid  = threadIdx.x;
    const int bid  = blockIdx.x;
    const int i    = bid * 1024 + tid;

    if (tid == 0) sh_epoch = atomicAdd(&sync[1], 0);   // pre-arrival epoch

    const int v0 = (i < n) ? cnt[i] : 0;
    if (i < n) cnt[i] = 0;                             // self-clean
    const int lane = tid & 31;
    const int warp = tid >> 5;

    int x = v0;
#pragma unroll
    for (int o = 1; o < 32; o <<= 1) {
        int y = __shfl_up_sync(0xffffffffu, x, o);
        if (lane >= o) x += y;
    }
    if (lane == 31) warpsum[warp] = x;
    __syncthreads();                                   // orders sh_epoch too
    if (warp == 0) {
        int w = warpsum[lane];
#pragma unroll
        for (int o = 1; o < 32; o <<= 1) {
            int y = __shfl_up_sync(0xffffffffu, w, o);
            if (lane >= o) w += y;
        }
        warpsum[lane] = w;
    }
    __syncthreads();
    const int incl = x + (warp ? warpsum[warp - 1] : 0);

    if (tid == 1023) {
        part[bid] = incl;
        __threadfence();
        int ticket = atomicAdd(&sync[0], 1);           // monotonic tickets
        sh_flag = (((ticket + 1) % nblk) == 0);        // last of this call
    }
    __syncthreads();

    if (sh_flag) {
        int mine = 0;
        if (tid < nblk) {
            mine = atomicAdd(&part[tid], 0);
            p[tid] = mine;
        }
        __syncthreads();
#pragma unroll
        for (int o = 1; o < 128; o <<= 1) {
            int add = (tid < nblk && tid >= o) ? p[tid - o] : 0;
            __syncthreads();
            if (tid < nblk) p[tid] += add;
            __syncthreads();
        }
        if (tid < nblk) boff[tid] = p[tid] - mine;
        if (tid == nblk - 1) rowptr[n] = p[tid];
        __threadfence();
        if (tid == 0) atomicAdd(&sync[1], 1);          // release (epoch++)
    }

    if (tid == 0) {
        while (atomicAdd(&sync[1], 0) == sh_epoch) __nanosleep(64);
        sh_boff = atomicAdd(&boff[bid], 0);
    }
    __syncthreads();

    if (i < n) rowptr[i] = incl - v0 + sh_boff;
}

// ---------------------------------------------------------------------------
// ATOMIC-FREE placement: pos = rowptr[seg] + rank  (8 edges / thread for MLP)
// ---------------------------------------------------------------------------
__global__ void placeE_kernel(const int4* __restrict__ src4, const int4* __restrict__ dst4) {
    int i = blockIdx.x * blockDim.x + threadIdx.x;
    if (i >= NNZ / 8) return;
    int4 s0 = __ldg(&src4[i * 2 + 0]);
    int4 s1 = __ldg(&src4[i * 2 + 1]);
    int4 d0 = __ldg(&dst4[i * 2 + 0]);
    int4 d1 = __ldg(&dst4[i * 2 + 1]);
    ushort4 r0 = *reinterpret_cast<const ushort4*>(g_rank_e + i * 8);
    ushort4 r1 = *reinterpret_cast<const ushort4*>(g_rank_e + i * 8 + 4);
    int p0 = __ldg(&g_rowptr_e[d0.x]);
    int p1 = __ldg(&g_rowptr_e[d0.y]);
    int p2 = __ldg(&g_rowptr_e[d0.z]);
    int p3 = __ldg(&g_rowptr_e[d0.w]);
    int p4 = __ldg(&g_rowptr_e[d1.x]);
    int p5 = __ldg(&g_rowptr_e[d1.y]);
    int p6 = __ldg(&g_rowptr_e[d1.z]);
    int p7 = __ldg(&g_rowptr_e[d1.w]);
    g_src_by_e[p0 + r0.x] = s0.x;
    g_src_by_e[p1 + r0.y] = s0.y;
    g_src_by_e[p2 + r0.z] = s0.z;
    g_src_by_e[p3 + r0.w] = s0.w;
    g_src_by_e[p4 + r1.x] = s1.x;
    g_src_by_e[p5 + r1.y] = s1.y;
    g_src_by_e[p6 + r1.z] = s1.z;
    g_src_by_e[p7 + r1.w] = s1.w;
}

__global__ void placeV_kernel(const int4* __restrict__ src4, const int4* __restrict__ dst4) {
    int i = blockIdx.x * blockDim.x + threadIdx.x;
    if (i >= NNZ / 8) return;
    int4 s0 = __ldg(&src4[i * 2 + 0]);
    int4 s1 = __ldg(&src4[i * 2 + 1]);
    int4 d0 = __ldg(&dst4[i * 2 + 0]);
    int4 d1 = __ldg(&dst4[i * 2 + 1]);
    ushort4 r0 = *reinterpret_cast<const ushort4*>(g_rank_v + i * 8);
    ushort4 r1 = *reinterpret_cast<const ushort4*>(g_rank_v + i * 8 + 4);
    int p0 = __ldg(&g_rowptr_v[s0.x]);
    int p1 = __ldg(&g_rowptr_v[s0.y]);
    int p2 = __ldg(&g_rowptr_v[s0.z]);
    int p3 = __ldg(&g_rowptr_v[s0.w]);
    int p4 = __ldg(&g_rowptr_v[s1.x]);
    int p5 = __ldg(&g_rowptr_v[s1.y]);
    int p6 = __ldg(&g_rowptr_v[s1.z]);
    int p7 = __ldg(&g_rowptr_v[s1.w]);
    g_dst_by_v[p0 + r0.x] = d0.x;
    g_dst_by_v[p1 + r0.y] = d0.y;
    g_dst_by_v[p2 + r0.z] = d0.z;
    g_dst_by_v[p3 + r0.w] = d0.w;
    g_dst_by_v[p4 + r1.x] = d1.x;
    g_dst_by_v[p5 + r1.y] = d1.y;
    g_dst_by_v[p6 + r1.z] = d1.z;
    g_dst_by_v[p7 + r1.w] = d1.w;
}

// ---------------------------------------------------------------------------
// Stage 1: warp per hyperedge (16 lanes x uint4, warp-halves alternate edges)
// ---------------------------------------------------------------------------
__global__ __launch_bounds__(256) void seg1_kernel(const float* __restrict__ degE,
                                                   const float* __restrict__ Wbuf) {
    int gid  = blockIdx.x * blockDim.x + threadIdx.x;
    int e    = gid >> 5;
    int lane = gid & 31;
    if (e >= N_HEDGES) return;
    int half = lane >> 4;
    int sub  = lane & 15;

    int beg = g_rowptr_e[e];
    int end = g_rowptr_e[e + 1];
    const uint4* Xh4 = reinterpret_cast<const uint4*>(g_Xh);

    float acc[8];
#pragma unroll
    for (int j = 0; j < 8; j++) acc[j] = 0.f;

    int i = beg + half;
    for (; i + 6 < end; i += 8) {
        int s0 = __ldg(&g_src_by_e[i + 0]);
        int s1 = __ldg(&g_src_by_e[i + 2]);
        int s2 = __ldg(&g_src_by_e[i + 4]);
        int s3 = __ldg(&g_src_by_e[i + 6]);
        uint4 u0 = __ldg(&Xh4[(size_t)s0 * 16 + sub]);
        uint4 u1 = __ldg(&Xh4[(size_t)s1 * 16 + sub]);
        uint4 u2 = __ldg(&Xh4[(size_t)s2 * 16 + sub]);
        uint4 u3 = __ldg(&Xh4[(size_t)s3 * 16 + sub]);
#pragma unroll
        for (int j = 0; j < 4; j++) {
            uint4 u = (j == 0) ? u0 : (j == 1) ? u1 : (j == 2) ? u2 : u3;
            const __half2* h = reinterpret_cast<const __half2*>(&u);
#pragma unroll
            for (int q = 0; q < 4; q++) {
                float2 f = __half22float2(h[q]);
                acc[q * 2]     += f.x;
                acc[q * 2 + 1] += f.y;
            }
        }
    }
    for (; i < end; i += 2) {
        int s = __ldg(&g_src_by_e[i]);
        uint4 u = __ldg(&Xh4[(size_t)s * 16 + sub]);
        const __half2* h = reinterpret_cast<const __half2*>(&u);
#pragma unroll
        for (int q = 0; q < 4; q++) {
            float2 f = __half22float2(h[q]);
            acc[q * 2]     += f.x;
            acc[q * 2 + 1] += f.y;
        }
    }

#pragma unroll
    for (int j = 0; j < 8; j++)
        acc[j] += __shfl_xor_sync(0xffffffffu, acc[j], 16);

    if (half == 0) {
        float sc = degE[e] * Wbuf[e];
        __half2 h[4];
#pragma unroll
        for (int q = 0; q < 4; q++)
            h[q] = __floats2half2_rn(acc[q * 2] * sc, acc[q * 2 + 1] * sc);
        *reinterpret_cast<uint4*>(g_Yh + (size_t)e * CH + sub * 8) =
            *reinterpret_cast<uint4*>(h);
    }
}

// ---------------------------------------------------------------------------
// HMMA GEMM: Zh = Yh @ Wh (fp16 in, fp32 accum, fp16 out)
// ---------------------------------------------------------------------------
#define GS 136

__global__ __launch_bounds__(256) void gemm_hmma_kernel() {
    extern __shared__ __half dsm[];
    __half* As = dsm;
    __half* Bs = dsm + 128 * GS;

    const int tid  = threadIdx.x;
    const int warp = tid >> 5;
    const int lane = tid & 31;
    const int row0 = blockIdx.x * 128;

    for (int t = tid; t < 128 * 16; t += 256) {
        int r = t >> 4;
        int c = (t & 15) * 8;
        uint4 v = make_uint4(0, 0, 0, 0);
        if (row0 + r < N_HEDGES)
            v = *reinterpret_cast<const uint4*>(g_Yh + (size_t)(row0 + r) * CH + c);
        *reinterpret_cast<uint4*>(&As[r * GS + c]) = v;
        *reinterpret_cast<uint4*>(&Bs[r * GS + c]) =
            *reinterpret_cast<const uint4*>(g_Wh + (size_t)r * CH + c);
    }
    __syncthreads();

    const int m0 = warp * 16;
    float acc[16][4];
#pragma unroll
    for (int t = 0; t < 16; t++)
#pragma unroll
        for (int j = 0; j < 4; j++) acc[t][j] = 0.f;

#pragma unroll
    for (int k0 = 0; k0 < 128; k0 += 16) {
        uint32_t a[4];
        {
            uint32_t addr = (uint32_t)__cvta_generic_to_shared(
                &As[(m0 + (lane & 15)) * GS + k0 + (lane >> 4) * 8]);
            asm volatile("ldmatrix.sync.aligned.m8n8.x4.shared.b16 {%0,%1,%2,%3}, [%4];"
                         : "=r"(a[0]), "=r"(a[1]), "=r"(a[2]), "=r"(a[3]) : "r"(addr));
        }
#pragma unroll
        for (int n0 = 0; n0 < 128; n0 += 16) {
            uint32_t b[4];
            uint32_t addr = (uint32_t)__cvta_generic_to_shared(
                &Bs[(k0 + (lane & 15)) * GS + n0 + (lane >> 4) * 8]);
            asm volatile("ldmatrix.sync.aligned.m8n8.x4.trans.shared.b16 {%0,%1,%2,%3}, [%4];"
                         : "=r"(b[0]), "=r"(b[1]), "=r"(b[2]), "=r"(b[3]) : "r"(addr));
            int t0 = n0 >> 3;
            asm volatile("mma.sync.aligned.m16n8k16.row.col.f32.f16.f16.f32 "
                         "{%0,%1,%2,%3},{%4,%5,%6,%7},{%8,%9},{%0,%1,%2,%3};"
                         : "+f"(acc[t0][0]), "+f"(acc[t0][1]), "+f"(acc[t0][2]), "+f"(acc[t0][3])
                         : "r"(a[0]), "r"(a[1]), "r"(a[2]), "r"(a[3]), "r"(b[0]), "r"(b[1]));
            asm volatile("mma.sync.aligned.m16n8k16.row.col.f32.f16.f16.f32 "
                         "{%0,%1,%2,%3},{%4,%5,%6,%7},{%8,%9},{%0,%1,%2,%3};"
                         : "+f"(acc[t0+1][0]), "+f"(acc[t0+1][1]), "+f"(acc[t0+1][2]), "+f"(acc[t0+1][3])
                         : "r"(a[0]), "r"(a[1]), "r"(a[2]), "r"(a[3]), "r"(b[2]), "r"(b[3]));
        }
    }

    const int groupID = lane >> 2;
    const int tig     = lane & 3;
    const int rowA = row0 + m0 + groupID;
    const int rowB = rowA + 8;
#pragma unroll
    for (int t = 0; t < 16; t++) {
        int col = t * 8 + tig * 2;
        if (rowA < N_HEDGES)
            *reinterpret_cast<__half2*>(g_Zh + (size_t)rowA * CH + col) =
                __floats2half2_rn(acc[t][0], acc[t][1]);
        if (rowB < N_HEDGES)
            *reinterpret_cast<__half2*>(g_Zh + (size_t)rowB * CH + col) =
                __floats2half2_rn(acc[t][2], acc[t][3]);
    }
}

// ---------------------------------------------------------------------------
// Stage 2: warp per node, 8-stride unroll (4 gathers in flight per half),
// int32 index stream (scattered-store width lesson from round 11 respected).
// ---------------------------------------------------------------------------
__global__ __launch_bounds__(256) void seg2_kernel(const float* __restrict__ degV,
                                                   float* __restrict__ out) {
    int gid  = blockIdx.x * blockDim.x + threadIdx.x;
    int v    = gid >> 5;
    int lane = gid & 31;
    if (v >= N_NODES) return;
    int half = lane >> 4;
    int sub  = lane & 15;

    int beg = g_rowptr_v[v];
    int end = g_rowptr_v[v + 1];
    const uint4* Zh4 = reinterpret_cast<const uint4*>(g_Zh);

    float acc[8];
#pragma unroll
    for (int j = 0; j < 8; j++) acc[j] = 0.f;

    int i = beg + half;
    for (; i + 6 < end; i += 8) {
        int d0 = __ldg(&g_dst_by_v[i + 0]);
        int d1 = __ldg(&g_dst_by_v[i + 2]);
        int d2 = __ldg(&g_dst_by_v[i + 4]);
        int d3 = __ldg(&g_dst_by_v[i + 6]);
        uint4 u0 = __ldg(&Zh4[(size_t)d0 * 16 + sub]);
        uint4 u1 = __ldg(&Zh4[(size_t)d1 * 16 + sub]);
        uint4 u2 = __ldg(&Zh4[(size_t)d2 * 16 + sub]);
        uint4 u3 = __ldg(&Zh4[(size_t)d3 * 16 + sub]);
#pragma unroll
        for (int j = 0; j < 4; j++) {
            uint4 u = (j == 0) ? u0 : (j == 1) ? u1 : (j == 2) ? u2 : u3;
            const __half2* h = reinterpret_cast<const __half2*>(&u);
#pragma unroll
            for (int q = 0; q < 4; q++) {
                float2 f = __half22float2(h[q]);
                acc[q * 2]     += f.x;
                acc[q * 2 + 1] += f.y;
            }
        }
    }
    for (; i < end; i += 2) {
        int d = __ldg(&g_dst_by_v[i]);
        uint4 u = __ldg(&Zh4[(size_t)d * 16 + sub]);
        const __half2* h = reinterpret_cast<const __half2*>(&u);
#pragma unroll
        for (int q = 0; q < 4; q++) {
            float2 f = __half22float2(h[q]);
            acc[q * 2]     += f.x;
            acc[q * 2 + 1] += f.y;
        }
    }

#pragma unroll
    for (int j = 0; j < 8; j++)
        acc[j] += __shfl_xor_sync(0xffffffffu, acc[j], 16);

    if (half == 0) {
        float sc = degV[v];
        float* o = out + (size_t)v * CH + sub * 8;
        *reinterpret_cast<float4*>(o) =
            make_float4(acc[0] * sc, acc[1] * sc, acc[2] * sc, acc[3] * sc);
        *reinterpret_cast<float4*>(o + 4) =
            make_float4(acc[4] * sc, acc[5] * sc, acc[6] * sc, acc[7] * sc);
    }
}

// ---------------------------------------------------------------------------
// Launch: histE first on main (no memsets); V-chain on s2 after histE;
// converts on s1 under histE.
// ---------------------------------------------------------------------------
extern "C" void kernel_launch(void* const* d_in, const int* in_sizes, int n_in,
                              void* d_out, int out_size) {
    const float* X    = (const float*)d_in[0];
    const float* Wlin = (const float*)d_in[1];
    const float* degE = (const float*)d_in[2];
    const float* degV = (const float*)d_in[3];
    const float* Wbuf = (const float*)d_in[4];
    const int*   src  = (const int*)d_in[5];
    const int*   dst  = (const int*)d_in[6];
    float*       out  = (float*)d_out;

    static cudaStream_t s1 = nullptr, s2 = nullptr;
    static cudaEvent_t evFork = nullptr, evX = nullptr, evV = nullptr, evHE = nullptr;
    if (!s1) {
        cudaStreamCreateWithFlags(&s1, cudaStreamNonBlocking);
        cudaStreamCreateWithFlags(&s2, cudaStreamNonBlocking);
        cudaEventCreateWithFlags(&evFork, cudaEventDisableTiming);
        cudaEventCreateWithFlags(&evX,    cudaEventDisableTiming);
        cudaEventCreateWithFlags(&evV,    cudaEventDisableTiming);
        cudaEventCreateWithFlags(&evHE,   cudaEventDisableTiming);
    }

    int *p_cnt_e, *p_cnt_v, *p_sync_e, *p_sync_v;
    int *p_rowptr_e, *p_rowptr_v;
    int *p_part_e, *p_boff_e, *p_part_v, *p_boff_v;
    cudaGetSymbolAddress((void**)&p_cnt_e,    g_cnt_e);
    cudaGetSymbolAddress((void**)&p_cnt_v,    g_cnt_v);
    cudaGetSymbolAddress((void**)&p_sync_e,   g_sync_e);
    cudaGetSymbolAddress((void**)&p_sync_v,   g_sync_v);
    cudaGetSymbolAddress((void**)&p_rowptr_e, g_rowptr_e);
    cudaGetSymbolAddress((void**)&p_rowptr_v, g_rowptr_v);
    cudaGetSymbolAddress((void**)&p_part_e,   g_part_e);
    cudaGetSymbolAddress((void**)&p_boff_e,   g_boff_e);
    cudaGetSymbolAddress((void**)&p_part_v,   g_part_v);
    cudaGetSymbolAddress((void**)&p_boff_v,   g_boff_v);

    cudaFuncSetAttribute(gemm_hmma_kernel,
                         cudaFuncAttributeMaxDynamicSharedMemorySize, 69632);

    const int nEdgeBlk4 = (NNZ / 4 + 255) / 256;
    const int nEdgeBlk8 = (NNZ / 8 + 255) / 256;

    // fork
    cudaEventRecord(evFork, 0);
    cudaStreamWaitEvent(s1, evFork, 0);
    cudaStreamWaitEvent(s2, evFork, 0);

    // s1: fp16 converts (hidden under histE)
    {
        size_t nThreads = (size_t)N_NODES * CH / 8 + (size_t)CH * CH / 8;
        convertAll_kernel<<<(int)((nThreads + 255) / 256), 256, 0, s1>>>(X, Wlin);
    }
    cudaEventRecord(evX, s1);

    // main: histE starts immediately (counters pre-zeroed by design)
    histE_kernel<<<nEdgeBlk4, 256>>>((const int4*)dst);
    cudaEventRecord(evHE, 0);

    // s2: V-chain AFTER histE; overlaps scanE/placeE/seg1/gemm on main.
    cudaStreamWaitEvent(s2, evHE, 0);
    histV_kernel<<<nEdgeBlk4, 256, 0, s2>>>((const int4*)src);
    scan_kernel<<<NB_V, 1024, 0, s2>>>(p_cnt_v, N_NODES, p_rowptr_v,
                                       p_part_v, p_boff_v, p_sync_v, NB_V);
    placeV_kernel<<<nEdgeBlk8, 256, 0, s2>>>((const int4*)src, (const int4*)dst);
    cudaEventRecord(evV, s2);

    // main: E-side scan + place (atomic-free), then compute chain
    scan_kernel<<<NB_E, 1024>>>(p_cnt_e, N_HEDGES, p_rowptr_e,
                                p_part_e, p_boff_e, p_sync_e, NB_E);
    placeE_kernel<<<nEdgeBlk8, 256>>>((const int4*)src, (const int4*)dst);

    cudaStreamWaitEvent(0, evX, 0);
    seg1_kernel<<<(N_HEDGES * 32 + 255) / 256, 256>>>(degE, Wbuf);
    gemm_hmma_kernel<<<(N_HEDGES + 127) / 128, 256, 69632>>>();

    cudaStreamWaitEvent(0, evV, 0);
    seg2_kernel<<<(N_NODES * 32 + 255) / 256, 256>>>(degV, out);
}